// round 13
// baseline (speedup 1.0000x reference)
#include <cuda_runtime.h>
#include <math.h>
#include <cstdint>
#include <cstddef>

#define BSZ   16
#define LDOC  1024
#define NNODE 64
#define LCH   32
#define HDIM  1024

// ---------------- scratch (device globals; no allocations allowed) ----------
__device__ float g_attn[32768u * 1024u];     // node_emb @ weightnode  [32768,1024]
__device__ float g_lastdoc[BSZ * HDIM];
__device__ float g_q[BSZ * HDIM];            // relu(last_doc@W2)*v2
__device__ float g_scorep[8u * 32768u];      // per-colblock partial scores
__device__ float g_ni0[BSZ * NNODE * HDIM];
__device__ float g_ni1[BSZ * NNODE * HDIM];
__device__ float g_g[BSZ * NNODE * HDIM];    // relu(ni @ W1)
__device__ float g_r2W0[BSZ * NNODE * HDIM]; // relu(output@W0)*v0
__device__ float g_proj[BSZ * NNODE * HDIM]; // output @ update3
__device__ float g_r1W0[16384u * 1024u];     // relu(doc@W0)
__device__ int   g_fm[BSZ * NNODE];          // final mask (rowsum(edge)==0)

// ---------------- packed f32x2 + cp.async helpers ----------------------------
__device__ __forceinline__ void ffma2(unsigned long long& d,
                                      unsigned long long a,
                                      unsigned long long b)
{
    asm("fma.rn.f32x2 %0, %1, %2, %0;" : "+l"(d) : "l"(a), "l"(b));
}
__device__ __forceinline__ unsigned long long dup2(float x)
{
    unsigned long long d;
    asm("mov.b64 %0, {%1, %1};" : "=l"(d) : "f"(x));
    return d;
}
union U64F2 { unsigned long long u; float2 f; };

__device__ __forceinline__ uint32_t smem_u32(const void* p) {
    uint32_t a;
    asm("{ .reg .u64 t; cvta.to.shared.u64 t, %1; cvt.u32.u64 %0, t; }" : "=r"(a) : "l"(p));
    return a;
}
__device__ __forceinline__ void cpasync16(uint32_t dst, const float* src) {
    asm volatile("cp.async.cg.shared.global [%0], [%1], 16;" :: "r"(dst), "l"(src));
}
#define CP_COMMIT() asm volatile("cp.async.commit_group;" ::: "memory")
#define CP_WAIT0()  asm volatile("cp.async.wait_group 0;" ::: "memory")

// ---------------- 64x128x32 FFMA2 GEMM body (device template) ----------------
// A: reg-prefetch + transpose STS (post-math). B: cp.async direct (no transform).
// MODE 0: C = A@B ; 1: relu ; 2: relu*v[col] ; 3: fused score reduce vs q
// Dynamic smem layout (floats): As[2][32][68] then Bs[2][32][132]  (50 KB)
#define A_BUF_F  2176          // 32*68
#define B_BUF_F  4224          // 32*132
#define B_OFF_F  4352          // 2*A_BUF_F
#define SMEM_GB  ((2*A_BUF_F + 2*B_BUF_F) * 4)   // 51200 bytes

template<int MODE>
__device__ __forceinline__
void gemm_body(const float* __restrict__ A, const float* __restrict__ B,
               float* __restrict__ C, int M, int N, int K,
               const float* __restrict__ vvec,
               const float* __restrict__ qvec,
               float* __restrict__ scoreOut, int bShift, int bm)
{
    extern __shared__ __align__(16) float smf[];

    const int tid = threadIdx.x;
    const int tx = tid & 15, ty = tid >> 4;       // ty 0..7
    const int bn = blockIdx.x;
    const int m0 = bm * 64;

    const int aRow = tid >> 1;          // 0..63
    const int aK   = (tid & 1) << 4;    // 0 / 16
    const int bk   = tid >> 5;          // 0..3 (warp id)
    const int bCol = (tid & 31) << 2;   // 0..124

    const float* Ab = A + (size_t)m0 * K;
    const float* Bb = B + (size_t)bn * 128;
    const uint32_t baseB = smem_u32(smf + B_OFF_F);

    unsigned long long acc2[8][4];
#pragma unroll
    for (int j = 0; j < 8; j++)
#pragma unroll
        for (int ip = 0; ip < 4; ip++) acc2[j][ip] = 0ull;

    const int T = K >> 5;
    float4 av[4];

    auto ldgA = [&](int t) {
        const int k0 = t * 32;
#pragma unroll
        for (int j = 0; j < 4; j++)
            av[j] = *(const float4*)(Ab + (size_t)aRow * K + k0 + aK + j * 4);
    };
    auto stsA = [&](int buf) {
        float* As = smf + buf * A_BUF_F;
#pragma unroll
        for (int j = 0; j < 4; j++) {
            As[(aK + j * 4 + 0) * 68 + aRow] = av[j].x;
            As[(aK + j * 4 + 1) * 68 + aRow] = av[j].y;
            As[(aK + j * 4 + 2) * 68 + aRow] = av[j].z;
            As[(aK + j * 4 + 3) * 68 + aRow] = av[j].w;
        }
    };
    auto cpB = [&](int t, int buf) {
        const int k0 = t * 32;
#pragma unroll
        for (int j = 0; j < 8; j++)
            cpasync16(baseB + buf * (B_BUF_F * 4) + (bk + 4 * j) * 528 + bCol * 4,
                      Bb + (size_t)(k0 + bk + 4 * j) * N + bCol);
    };

    // prologue: tile 0 into buf 0
    cpB(0, 0); CP_COMMIT();
    ldgA(0); stsA(0);

    for (int t = 0; t < T; t++) {
        CP_WAIT0();                      // B(t) landed
        __syncthreads();                 // A(t) STS visible; all reads of nxt buf done
        const int buf = t & 1;
        if (t + 1 < T) {
            cpB(t + 1, buf ^ 1); CP_COMMIT();   // streams during math
            ldgA(t + 1);                         // in flight during math
        }
        const float* Asb = smf + buf * A_BUF_F;
        const float* Bsb = smf + B_OFF_F + buf * B_BUF_F;
#pragma unroll
        for (int k = 0; k < 32; k++) {
            ulonglong2 aP01 = *(const ulonglong2*)&Asb[k * 68 + ty * 4];
            ulonglong2 aP23 = *(const ulonglong2*)&Asb[k * 68 + 32 + ty * 4];
            float4 rb0 = *(const float4*)&Bsb[k * 132 + tx * 4];
            float4 rb1 = *(const float4*)&Bsb[k * 132 + 64 + tx * 4];
            unsigned long long bd[8];
            bd[0] = dup2(rb0.x); bd[1] = dup2(rb0.y);
            bd[2] = dup2(rb0.z); bd[3] = dup2(rb0.w);
            bd[4] = dup2(rb1.x); bd[5] = dup2(rb1.y);
            bd[6] = dup2(rb1.z); bd[7] = dup2(rb1.w);
#pragma unroll
            for (int j = 0; j < 8; j++) {
                ffma2(acc2[j][0], aP01.x, bd[j]);
                ffma2(acc2[j][1], aP01.y, bd[j]);
                ffma2(acc2[j][2], aP23.x, bd[j]);
                ffma2(acc2[j][3], aP23.y, bd[j]);
            }
        }
        if (t + 1 < T) stsA(buf ^ 1);    // into opposite buffer (others still read cur)
    }
    __syncthreads();                     // all math done (MODE 3 reuses smem)

    float acc[8][8];
#pragma unroll
    for (int j = 0; j < 8; j++)
#pragma unroll
        for (int ip = 0; ip < 4; ip++) {
            U64F2 u; u.u = acc2[j][ip];
            acc[ip * 2 + 0][j] = u.f.x;
            acc[ip * 2 + 1][j] = u.f.y;
        }

    int rl[8];
#pragma unroll
    for (int i = 0; i < 4; i++) { rl[i] = ty * 4 + i; rl[i + 4] = 32 + ty * 4 + i; }

    if constexpr (MODE <= 2) {
        float vv[8];
        if constexpr (MODE == 2) {
            *(float4*)&vv[0] = *(const float4*)&vvec[bn * 128 + tx * 4];
            *(float4*)&vv[4] = *(const float4*)&vvec[bn * 128 + 64 + tx * 4];
        }
#pragma unroll
        for (int i = 0; i < 8; i++) {
            size_t rowOff = (size_t)(m0 + rl[i]) * N + bn * 128;
            float o[8];
#pragma unroll
            for (int j = 0; j < 8; j++) {
                float x = acc[i][j];
                if constexpr (MODE >= 1) x = fmaxf(x, 0.f);
                if constexpr (MODE == 2) x *= vv[j];
                o[j] = x;
            }
            *(float4*)(C + rowOff + tx * 4)      = *(float4*)&o[0];
            *(float4*)(C + rowOff + 64 + tx * 4) = *(float4*)&o[4];
        }
    } else {
        const int b = m0 >> bShift;       // batch of this row block
        float q8[8];
        *(float4*)&q8[0] = *(const float4*)&qvec[b * HDIM + bn * 128 + tx * 4];
        *(float4*)&q8[4] = *(const float4*)&qvec[b * HDIM + bn * 128 + 64 + tx * 4];
        float part[8];
#pragma unroll
        for (int i = 0; i < 8; i++) {
            float s = 0.f;
#pragma unroll
            for (int j = 0; j < 8; j++) s += fmaxf(acc[i][j], 0.f) * q8[j];
            part[i] = s;
        }
        // deterministic block reduction (fixed order), reuse smem as [64][16]
        float* redm = smf;
#pragma unroll
        for (int i = 0; i < 8; i++) redm[rl[i] * 16 + tx] = part[i];
        __syncthreads();
        if (tid < 64) {
            float s = 0.f;
#pragma unroll
            for (int x = 0; x < 16; x++) s += redm[tid * 16 + x];
            scoreOut[(size_t)bn * M + m0 + tid] = s;
        }
    }
}

// single-mode wrapper (G1, G2, W1 rounds)
template<int MODE>
__global__ __launch_bounds__(128, 3)
void sgemm128(const float* __restrict__ A, const float* __restrict__ B,
              float* __restrict__ C, int M, int N, int K,
              const float* __restrict__ vvec,
              const float* __restrict__ qvec,
              float* __restrict__ scoreOut, int bShift)
{
    gemm_body<MODE>(A, B, C, M, N, K, vvec, qvec, scoreOut, bShift, blockIdx.y);
}

// dual-mode kernel: two independent GEMM jobs drained as one CTA pool
// blockIdx.y < (M1>>6): job1 (MODE_A); else job2 (MODE_B)
template<int MODE_A, int MODE_B>
__global__ __launch_bounds__(128, 3)
void sgemm_dual(const float* __restrict__ A1, const float* __restrict__ B1,
                float* __restrict__ C1, int M1,
                const float* __restrict__ A2, const float* __restrict__ B2,
                float* __restrict__ C2, int M2,
                int N, int K, const float* __restrict__ vvec)
{
    const int half = M1 >> 6;
    if ((int)blockIdx.y < half)
        gemm_body<MODE_A>(A1, B1, C1, M1, N, K, vvec, nullptr, nullptr, 0, blockIdx.y);
    else
        gemm_body<MODE_B>(A2, B2, C2, M2, N, K, vvec, nullptr, nullptr, 0, blockIdx.y - half);
}

// ---------------- small kernels ---------------------------------------------
__global__ void k_lastdoc(const float* __restrict__ doc, const int* __restrict__ dmask)
{
    int b = blockIdx.x, t = threadIdx.x;
    __shared__ int s_len;
    if (t == 0) s_len = 0;
    __syncthreads();
    int c = 0;
    for (int i = t; i < LDOC; i += 256) c += (dmask[b * LDOC + i] == 0);
#pragma unroll
    for (int o = 16; o; o >>= 1) c += __shfl_down_sync(0xffffffffu, c, o);
    if ((t & 31) == 0) atomicAdd(&s_len, c);
    __syncthreads();
    int idx = s_len - 1;
    for (int i = t; i < HDIM; i += 256)
        g_lastdoc[b * HDIM + i] = doc[((size_t)b * LDOC + idx) * HDIM + i];
}

__global__ void k_q(const float* __restrict__ W2, const float* __restrict__ v2)
{
    int c = blockIdx.x * 256 + threadIdx.x;
    int b = blockIdx.y;
    const float* ld = &g_lastdoc[b * HDIM];
    float acc = 0.f;
    for (int k = 0; k < HDIM; k += 4) {
        float4 x = *(const float4*)&ld[k];
        acc += x.x * W2[(size_t)(k + 0) * HDIM + c];
        acc += x.y * W2[(size_t)(k + 1) * HDIM + c];
        acc += x.z * W2[(size_t)(k + 2) * HDIM + c];
        acc += x.w * W2[(size_t)(k + 3) * HDIM + c];
    }
    g_q[b * HDIM + c] = fmaxf(acc, 0.f) * v2[c];
}

// softmax over L=32 (mask -> -inf) + weighted sum of attn_node -> node_initial
__global__ __launch_bounds__(256)
void k_nodeinit(const unsigned char* __restrict__ nmask)
{
    int p = blockIdx.x;       // 0..1023 = (b*64+n)
    int t = threadIdx.x;
    __shared__ float e[LCH];
    if (t < 32) {
        float s = 0.f;
#pragma unroll
        for (int cb = 0; cb < 8; cb++) s += g_scorep[cb * 32768 + p * LCH + t];
        if (nmask[p * LCH + t]) s = -INFINITY;
        float mx = s;
#pragma unroll
        for (int o = 16; o; o >>= 1) mx = fmaxf(mx, __shfl_xor_sync(0xffffffffu, mx, o));
        float ex = expf(s - mx);
        float sm = ex;
#pragma unroll
        for (int o = 16; o; o >>= 1) sm += __shfl_xor_sync(0xffffffffu, sm, o);
        e[t] = ex / sm;
    }
    __syncthreads();
    float4 acc = make_float4(0.f, 0.f, 0.f, 0.f);
    const float4* ap = (const float4*)&g_attn[(size_t)p * LCH * HDIM];
#pragma unroll 4
    for (int l = 0; l < LCH; l++) {
        float w = e[l];
        float4 x = ap[l * 256 + t];
        acc.x += w * x.x; acc.y += w * x.y; acc.z += w * x.z; acc.w += w * x.w;
    }
    ((float4*)g_ni0)[(size_t)p * 256 + t] = acc;
}

// one GAT round: scores from g=relu(ni@W1), edge mask (NEG_BIG), softmax, aggregate ni
__global__ __launch_bounds__(256)
void k_round(const float* __restrict__ g, const float* __restrict__ v1,
             const int* __restrict__ edge,
             const float* __restrict__ ni_in, float* __restrict__ ni_out)
{
    int bi = blockIdx.x;              // (b,i) flattened
    int b = bi >> 6, i = bi & 63;
    int t = threadIdx.x;
    __shared__ __align__(16) float gv[HDIM];
    __shared__ float sc[64];
    __shared__ float al[64];
    {
        float4 x  = ((const float4*)g)[(size_t)bi * 256 + t];
        float4 vv = ((const float4*)v1)[t];
        *(float4*)&gv[t * 4] = make_float4(x.x * vv.x, x.y * vv.y, x.z * vv.z, x.w * vv.w);
    }
    __syncthreads();
    int j = t >> 2, sub = t & 3;
    const float* gj = g + (size_t)(b * 64 + j) * HDIM;
    float acc = 0.f;
#pragma unroll 8
    for (int it = 0; it < 64; it++) {
        int h = it * 16 + sub * 4;
        float4 a  = *(const float4*)&gj[h];
        float4 bb = *(const float4*)&gv[h];
        acc += a.x * bb.x + a.y * bb.y + a.z * bb.z + a.w * bb.w;
    }
    acc += __shfl_xor_sync(0xffffffffu, acc, 1);
    acc += __shfl_xor_sync(0xffffffffu, acc, 2);
    if (sub == 0) sc[j] = acc;
    __syncthreads();
    if (t < 32) {
        const int* er = edge + (size_t)(b * 64 + i) * 64;
        float s0 = sc[t], s1 = sc[t + 32];
        if (er[t] == 0)      s0 = -100000.0f;
        if (er[t + 32] == 0) s1 = -100000.0f;
        float mx = fmaxf(s0, s1);
#pragma unroll
        for (int o = 16; o; o >>= 1) mx = fmaxf(mx, __shfl_xor_sync(0xffffffffu, mx, o));
        float e0 = expf(s0 - mx), e1 = expf(s1 - mx);
        float sm = e0 + e1;
#pragma unroll
        for (int o = 16; o; o >>= 1) sm += __shfl_xor_sync(0xffffffffu, sm, o);
        float inv = 1.f / sm;
        al[t] = e0 * inv; al[t + 32] = e1 * inv;
    }
    __syncthreads();
    float4 a4 = make_float4(0.f, 0.f, 0.f, 0.f);
    const float4* nib = (const float4*)(ni_in + (size_t)b * 64 * HDIM);
#pragma unroll 4
    for (int jj = 0; jj < 64; jj++) {
        float w = al[jj];
        float4 x = nib[jj * 256 + t];
        a4.x += w * x.x; a4.y += w * x.y; a4.z += w * x.z; a4.w += w * x.w;
    }
    ((float4*)ni_out)[(size_t)bi * 256 + t] = a4;
}

__global__ void k_fmask(const int* __restrict__ edge)
{
    int t = threadIdx.x;
    const int* er = edge + (size_t)t * 64;
    int s = 0;
#pragma unroll 8
    for (int jj = 0; jj < 64; jj++) s += er[jj];
    g_fm[t] = (s == 0);
}

// fused doc->node attention: 32 doc rows/block: scores -> softmax -> alpha@proj (+= out)
__global__ __launch_bounds__(256)
void k_docattn(float* __restrict__ out)
{
    const int bidx = blockIdx.x;
    const int b = bidx >> 5;
    const int ld0 = (bidx & 31) * 32;
    const int tid = threadIdx.x;
    const int tx = tid & 15, ty = tid >> 4;
    __shared__ __align__(16) float sAl[32][68];
    __shared__ __align__(16) float buf[8448];
    float* r1cT = buf;            // [64 k][36]
    float* r2cT = buf + 2304;     // [64 k][68]

    float acc0[4] = {0.f, 0.f, 0.f, 0.f};
    float acc1[4] = {0.f, 0.f, 0.f, 0.f};

    for (int kc = 0; kc < 16; kc++) {
#pragma unroll
        for (int it = 0; it < 2; it++) {
            int f = tid + it * 256;
            int row = f >> 4, c4 = f & 15;
            float4 v = *(const float4*)&g_r1W0[((size_t)(b * 1024 + ld0 + row)) * 1024 + kc * 64 + c4 * 4];
            r1cT[(c4 * 4 + 0) * 36 + row] = v.x;
            r1cT[(c4 * 4 + 1) * 36 + row] = v.y;
            r1cT[(c4 * 4 + 2) * 36 + row] = v.z;
            r1cT[(c4 * 4 + 3) * 36 + row] = v.w;
        }
#pragma unroll
        for (int it = 0; it < 4; it++) {
            int f = tid + it * 256;
            int jj = f >> 4, c4 = f & 15;
            float4 v = *(const float4*)&g_r2W0[((size_t)(b * 64 + jj)) * 1024 + kc * 64 + c4 * 4];
            r2cT[(c4 * 4 + 0) * 68 + jj] = v.x;
            r2cT[(c4 * 4 + 1) * 68 + jj] = v.y;
            r2cT[(c4 * 4 + 2) * 68 + jj] = v.z;
            r2cT[(c4 * 4 + 3) * 68 + jj] = v.w;
        }
        __syncthreads();
#pragma unroll
        for (int k = 0; k < 64; k++) {
            float a0 = r1cT[k * 36 + ty * 2];
            float a1 = r1cT[k * 36 + ty * 2 + 1];
            float4 bb = *(float4*)&r2cT[k * 68 + tx * 4];
            acc0[0] += a0 * bb.x; acc0[1] += a0 * bb.y; acc0[2] += a0 * bb.z; acc0[3] += a0 * bb.w;
            acc1[0] += a1 * bb.x; acc1[1] += a1 * bb.y; acc1[2] += a1 * bb.z; acc1[3] += a1 * bb.w;
        }
        __syncthreads();
    }
    *(float4*)&sAl[ty * 2][tx * 4]     = *(float4*)&acc0[0];
    *(float4*)&sAl[ty * 2 + 1][tx * 4] = *(float4*)&acc1[0];
    __syncthreads();

    {
        int w = tid >> 5, lane = tid & 31;
        int m0 = g_fm[b * 64 + lane];
        int m1 = g_fm[b * 64 + lane + 32];
#pragma unroll
        for (int r = 0; r < 4; r++) {
            int row = w * 4 + r;
            float v0 = sAl[row][lane];
            float v1 = sAl[row][lane + 32];
            if (m0) v0 = -INFINITY;
            if (m1) v1 = -INFINITY;
            float mx = fmaxf(v0, v1);
#pragma unroll
            for (int o = 16; o; o >>= 1) mx = fmaxf(mx, __shfl_xor_sync(0xffffffffu, mx, o));
            float e0 = expf(v0 - mx), e1 = expf(v1 - mx);
            float sm = e0 + e1;
#pragma unroll
            for (int o = 16; o; o >>= 1) sm += __shfl_xor_sync(0xffffffffu, sm, o);
            float inv = 1.f / sm;
            sAl[row][lane] = e0 * inv;
            sAl[row][lane + 32] = e1 * inv;
        }
    }
    __syncthreads();

    float* projc = buf;
    for (int nc = 0; nc < 8; nc++) {
#pragma unroll
        for (int it = 0; it < 8; it++) {
            int f = tid + it * 256;
            int jj = f >> 5, c4 = f & 31;
            float4 v = *(const float4*)&g_proj[((size_t)(b * 64 + jj)) * 1024 + nc * 128 + c4 * 4];
            *(float4*)&projc[jj * 132 + c4 * 4] = v;
        }
        __syncthreads();
        float o0[8] = {0.f,0.f,0.f,0.f,0.f,0.f,0.f,0.f};
        float o1[8] = {0.f,0.f,0.f,0.f,0.f,0.f,0.f,0.f};
#pragma unroll
        for (int jj = 0; jj < 64; jj++) {
            float a0 = sAl[ty * 2][jj];
            float a1 = sAl[ty * 2 + 1][jj];
            float4 p0 = *(float4*)&projc[jj * 132 + tx * 4];
            float4 p1 = *(float4*)&projc[jj * 132 + 64 + tx * 4];
            o0[0] += a0 * p0.x; o0[1] += a0 * p0.y; o0[2] += a0 * p0.z; o0[3] += a0 * p0.w;
            o0[4] += a0 * p1.x; o0[5] += a0 * p1.y; o0[6] += a0 * p1.z; o0[7] += a0 * p1.w;
            o1[0] += a1 * p0.x; o1[1] += a1 * p0.y; o1[2] += a1 * p0.z; o1[3] += a1 * p0.w;
            o1[4] += a1 * p1.x; o1[5] += a1 * p1.y; o1[6] += a1 * p1.z; o1[7] += a1 * p1.w;
        }
#pragma unroll
        for (int r = 0; r < 2; r++) {
            float* src = r ? o1 : o0;
            float* op = out + ((size_t)(b * 1024 + ld0 + ty * 2 + r)) * 1024 + nc * 128;
            float4 c0 = *(float4*)(op + tx * 4);
            c0.x += src[0]; c0.y += src[1]; c0.z += src[2]; c0.w += src[3];
            *(float4*)(op + tx * 4) = c0;
            float4 c1 = *(float4*)(op + 64 + tx * 4);
            c1.x += src[4]; c1.y += src[5]; c1.z += src[6]; c1.w += src[7];
            *(float4*)(op + 64 + tx * 4) = c1;
        }
        __syncthreads();
    }
}

// ---------------- launch -----------------------------------------------------
extern "C" void kernel_launch(void* const* d_in, const int* in_sizes, int n_in,
                              void* d_out, int out_size)
{
    const float* doc   = (const float*)d_in[0];
    const float* node  = (const float*)d_in[1];
    const float* Wn    = (const float*)d_in[2];
    const float* U3    = (const float*)d_in[3];
    const float* U4    = (const float*)d_in[4];
    const float* W2    = (const float*)d_in[5];
    const float* v2    = (const float*)d_in[6];
    const float* W1    = (const float*)d_in[7];
    const float* v1    = (const float*)d_in[8];
    const float* W0    = (const float*)d_in[9];
    const float* v0    = (const float*)d_in[10];
    const int* dmask   = (const int*)d_in[11];
    const unsigned char* nmask = (const unsigned char*)d_in[12];
    const int* edge    = (const int*)d_in[13];
    float* out = (float*)d_out;
    (void)in_sizes; (void)n_in; (void)out_size;

    float *p_attn, *p_scorep, *p_ni0, *p_ni1, *p_g, *p_r2, *p_proj, *p_r1, *p_q;
    cudaGetSymbolAddress((void**)&p_attn,   g_attn);
    cudaGetSymbolAddress((void**)&p_scorep, g_scorep);
    cudaGetSymbolAddress((void**)&p_ni0,    g_ni0);
    cudaGetSymbolAddress((void**)&p_ni1,    g_ni1);
    cudaGetSymbolAddress((void**)&p_g,      g_g);
    cudaGetSymbolAddress((void**)&p_r2,     g_r2W0);
    cudaGetSymbolAddress((void**)&p_proj,   g_proj);
    cudaGetSymbolAddress((void**)&p_r1,     g_r1W0);
    cudaGetSymbolAddress((void**)&p_q,      g_q);

    cudaFuncSetAttribute(sgemm128<0>, cudaFuncAttributeMaxDynamicSharedMemorySize, SMEM_GB);
    cudaFuncSetAttribute(sgemm128<1>, cudaFuncAttributeMaxDynamicSharedMemorySize, SMEM_GB);
    cudaFuncSetAttribute(sgemm128<3>, cudaFuncAttributeMaxDynamicSharedMemorySize, SMEM_GB);
    cudaFuncSetAttribute(sgemm_dual<0, 1>, cudaFuncAttributeMaxDynamicSharedMemorySize, SMEM_GB);
    cudaFuncSetAttribute(sgemm_dual<2, 0>, cudaFuncAttributeMaxDynamicSharedMemorySize, SMEM_GB);

    k_lastdoc<<<BSZ, 256>>>(doc, dmask);
    k_q<<<dim3(4, BSZ), 256>>>(W2, v2);

    // G1: attn_node = node_emb @ weightnode   [32768,1024]
    sgemm128<0><<<dim3(8, 512), 128, SMEM_GB>>>(node, Wn, p_attn, 32768, 1024, 1024,
                                                nullptr, nullptr, nullptr, 0);
    // G2: fused relu(attn_node @ W2) . q -> partial scores
    sgemm128<3><<<dim3(8, 512), 128, SMEM_GB>>>(p_attn, W2, nullptr, 32768, 1024, 1024,
                                                nullptr, p_q, p_scorep, 11);

    k_nodeinit<<<1024, 256>>>(nmask);

    // 3 GAT rounds
    const float* cur = p_ni0; float* nxt = p_ni1;
    for (int r = 0; r < 3; r++) {
        sgemm128<1><<<dim3(8, 16), 128, SMEM_GB>>>(cur, W1, p_g, 1024, 1024, 1024,
                                                   nullptr, nullptr, nullptr, 0);
        k_round<<<1024, 256>>>(p_g, v1, edge, cur, nxt);
        const float* tmp = cur; cur = nxt; nxt = (float*)tmp;
    }

    // node-side projections merged: r2 = relu(out@W0)*v0  +  proj = out@U3
    sgemm_dual<2, 0><<<dim3(8, 32), 128, SMEM_GB>>>(cur, W0, p_r2, 1024,
                                                    cur, U3, p_proj, 1024,
                                                    1024, 1024, v0);
    // doc-side merged: out = doc@U4  +  r1W0 = relu(doc@W0)  (one CTA pool, one tail)
    sgemm_dual<0, 1><<<dim3(8, 512), 128, SMEM_GB>>>(doc, U4, out, 16384,
                                                     doc, W0, p_r1, 16384,
                                                     1024, 1024, nullptr);

    k_fmask<<<1, 1024>>>(edge);
    k_docattn<<<512, 256>>>(out);
}

// round 14
// speedup vs baseline: 1.0811x; 1.0811x over previous
#include <cuda_runtime.h>
#include <math.h>
#include <cstdint>
#include <cstddef>

#define BSZ   16
#define LDOC  1024
#define NNODE 64
#define LCH   32
#define HDIM  1024

// ---------------- scratch (device globals; no allocations allowed) ----------
__device__ float g_attn[32768u * 1024u];     // node_emb @ weightnode  [32768,1024]
__device__ float g_lastdoc[BSZ * HDIM];
__device__ float g_q[BSZ * HDIM];            // relu(last_doc@W2)*v2
__device__ float g_scorep[8u * 32768u];      // per-colblock partial scores
__device__ float g_ni0[BSZ * NNODE * HDIM];
__device__ float g_ni1[BSZ * NNODE * HDIM];
__device__ float g_g[BSZ * NNODE * HDIM];    // relu(ni @ W1)
__device__ float g_r2W0[BSZ * NNODE * HDIM]; // relu(output@W0)*v0
__device__ float g_proj[BSZ * NNODE * HDIM]; // output @ update3
__device__ float g_r1W0[16384u * 1024u];     // relu(doc@W0)
__device__ float g_pk[8u * 1048576u];        // split-K partial buffers (8 x 4MB)
__device__ int   g_fm[BSZ * NNODE];          // final mask (rowsum(edge)==0)

// ---------------- packed f32x2 + cp.async helpers ----------------------------
__device__ __forceinline__ void ffma2(unsigned long long& d,
                                      unsigned long long a,
                                      unsigned long long b)
{
    asm("fma.rn.f32x2 %0, %1, %2, %0;" : "+l"(d) : "l"(a), "l"(b));
}
__device__ __forceinline__ unsigned long long dup2(float x)
{
    unsigned long long d;
    asm("mov.b64 %0, {%1, %1};" : "=l"(d) : "f"(x));
    return d;
}
union U64F2 { unsigned long long u; float2 f; };

__device__ __forceinline__ uint32_t smem_u32(const void* p) {
    uint32_t a;
    asm("{ .reg .u64 t; cvta.to.shared.u64 t, %1; cvt.u32.u64 %0, t; }" : "=r"(a) : "l"(p));
    return a;
}
__device__ __forceinline__ void cpasync16(uint32_t dst, const float* src) {
    asm volatile("cp.async.cg.shared.global [%0], [%1], 16;" :: "r"(dst), "l"(src));
}
#define CP_COMMIT() asm volatile("cp.async.commit_group;" ::: "memory")
#define CP_WAIT0()  asm volatile("cp.async.wait_group 0;" ::: "memory")

// ---------------- 64x128 FFMA2 GEMM body (device template) -------------------
// A: reg-prefetch + transpose STS (post-math). B: cp.async direct.
// MODE 0: C = A@B ; 1: relu ; 2: relu*v[col] ; 3: fused score reduce vs q
// kStart/kLen: K-chunk (split-K support); K remains the row stride of A.
#define A_BUF_F  2176          // 32*68
#define B_BUF_F  4224          // 32*132
#define B_OFF_F  4352          // 2*A_BUF_F
#define SMEM_GB  ((2*A_BUF_F + 2*B_BUF_F) * 4)   // 51200 bytes

template<int MODE>
__device__ __forceinline__
void gemm_body(const float* __restrict__ A, const float* __restrict__ B,
               float* __restrict__ C, int M, int N, int K,
               const float* __restrict__ vvec,
               const float* __restrict__ qvec,
               float* __restrict__ scoreOut, int bShift, int bm,
               int kStart, int kLen)
{
    extern __shared__ __align__(16) float smf[];

    const int tid = threadIdx.x;
    const int tx = tid & 15, ty = tid >> 4;       // ty 0..7
    const int bn = blockIdx.x;
    const int m0 = bm * 64;

    const int aRow = tid >> 1;          // 0..63
    const int aK   = (tid & 1) << 4;    // 0 / 16
    const int bk   = tid >> 5;          // 0..3 (warp id)
    const int bCol = (tid & 31) << 2;   // 0..124

    const float* Ab = A + (size_t)m0 * K;
    const float* Bb = B + (size_t)bn * 128;
    const uint32_t baseB = smem_u32(smf + B_OFF_F);

    unsigned long long acc2[8][4];
#pragma unroll
    for (int j = 0; j < 8; j++)
#pragma unroll
        for (int ip = 0; ip < 4; ip++) acc2[j][ip] = 0ull;

    const int T = kLen >> 5;
    float4 av[4];

    auto ldgA = [&](int t) {
        const int k0 = kStart + t * 32;
#pragma unroll
        for (int j = 0; j < 4; j++)
            av[j] = *(const float4*)(Ab + (size_t)aRow * K + k0 + aK + j * 4);
    };
    auto stsA = [&](int buf) {
        float* As = smf + buf * A_BUF_F;
#pragma unroll
        for (int j = 0; j < 4; j++) {
            As[(aK + j * 4 + 0) * 68 + aRow] = av[j].x;
            As[(aK + j * 4 + 1) * 68 + aRow] = av[j].y;
            As[(aK + j * 4 + 2) * 68 + aRow] = av[j].z;
            As[(aK + j * 4 + 3) * 68 + aRow] = av[j].w;
        }
    };
    auto cpB = [&](int t, int buf) {
        const int k0 = kStart + t * 32;
#pragma unroll
        for (int j = 0; j < 8; j++)
            cpasync16(baseB + buf * (B_BUF_F * 4) + (bk + 4 * j) * 528 + bCol * 4,
                      Bb + (size_t)(k0 + bk + 4 * j) * N + bCol);
    };

    // prologue: tile 0 into buf 0
    cpB(0, 0); CP_COMMIT();
    ldgA(0); stsA(0);

    for (int t = 0; t < T; t++) {
        CP_WAIT0();                      // B(t) landed
        __syncthreads();                 // A(t) STS visible; all reads of nxt buf done
        const int buf = t & 1;
        if (t + 1 < T) {
            cpB(t + 1, buf ^ 1); CP_COMMIT();   // streams during math
            ldgA(t + 1);                         // in flight during math
        }
        const float* Asb = smf + buf * A_BUF_F;
        const float* Bsb = smf + B_OFF_F + buf * B_BUF_F;
#pragma unroll
        for (int k = 0; k < 32; k++) {
            ulonglong2 aP01 = *(const ulonglong2*)&Asb[k * 68 + ty * 4];
            ulonglong2 aP23 = *(const ulonglong2*)&Asb[k * 68 + 32 + ty * 4];
            float4 rb0 = *(const float4*)&Bsb[k * 132 + tx * 4];
            float4 rb1 = *(const float4*)&Bsb[k * 132 + 64 + tx * 4];
            unsigned long long bd[8];
            bd[0] = dup2(rb0.x); bd[1] = dup2(rb0.y);
            bd[2] = dup2(rb0.z); bd[3] = dup2(rb0.w);
            bd[4] = dup2(rb1.x); bd[5] = dup2(rb1.y);
            bd[6] = dup2(rb1.z); bd[7] = dup2(rb1.w);
#pragma unroll
            for (int j = 0; j < 8; j++) {
                ffma2(acc2[j][0], aP01.x, bd[j]);
                ffma2(acc2[j][1], aP01.y, bd[j]);
                ffma2(acc2[j][2], aP23.x, bd[j]);
                ffma2(acc2[j][3], aP23.y, bd[j]);
            }
        }
        if (t + 1 < T) stsA(buf ^ 1);    // into opposite buffer (others still read cur)
    }
    __syncthreads();                     // all math done (MODE 3 reuses smem)

    float acc[8][8];
#pragma unroll
    for (int j = 0; j < 8; j++)
#pragma unroll
        for (int ip = 0; ip < 4; ip++) {
            U64F2 u; u.u = acc2[j][ip];
            acc[ip * 2 + 0][j] = u.f.x;
            acc[ip * 2 + 1][j] = u.f.y;
        }

    int rl[8];
#pragma unroll
    for (int i = 0; i < 4; i++) { rl[i] = ty * 4 + i; rl[i + 4] = 32 + ty * 4 + i; }

    if constexpr (MODE <= 2) {
        float vv[8];
        if constexpr (MODE == 2) {
            *(float4*)&vv[0] = *(const float4*)&vvec[bn * 128 + tx * 4];
            *(float4*)&vv[4] = *(const float4*)&vvec[bn * 128 + 64 + tx * 4];
        }
#pragma unroll
        for (int i = 0; i < 8; i++) {
            size_t rowOff = (size_t)(m0 + rl[i]) * N + bn * 128;
            float o[8];
#pragma unroll
            for (int j = 0; j < 8; j++) {
                float x = acc[i][j];
                if constexpr (MODE >= 1) x = fmaxf(x, 0.f);
                if constexpr (MODE == 2) x *= vv[j];
                o[j] = x;
            }
            *(float4*)(C + rowOff + tx * 4)      = *(float4*)&o[0];
            *(float4*)(C + rowOff + 64 + tx * 4) = *(float4*)&o[4];
        }
    } else {
        const int b = m0 >> bShift;       // batch of this row block
        float q8[8];
        *(float4*)&q8[0] = *(const float4*)&qvec[b * HDIM + bn * 128 + tx * 4];
        *(float4*)&q8[4] = *(const float4*)&qvec[b * HDIM + bn * 128 + 64 + tx * 4];
        float part[8];
#pragma unroll
        for (int i = 0; i < 8; i++) {
            float s = 0.f;
#pragma unroll
            for (int j = 0; j < 8; j++) s += fmaxf(acc[i][j], 0.f) * q8[j];
            part[i] = s;
        }
        // deterministic block reduction (fixed order), reuse smem as [64][16]
        float* redm = smf;
#pragma unroll
        for (int i = 0; i < 8; i++) redm[rl[i] * 16 + tx] = part[i];
        __syncthreads();
        if (tid < 64) {
            float s = 0.f;
#pragma unroll
            for (int x = 0; x < 16; x++) s += redm[tid * 16 + x];
            scoreOut[(size_t)bn * M + m0 + tid] = s;
        }
    }
}

// single-mode wrapper (G1, G2)
template<int MODE>
__global__ __launch_bounds__(128, 4)
void sgemm128(const float* __restrict__ A, const float* __restrict__ B,
              float* __restrict__ C, int M, int N, int K,
              const float* __restrict__ vvec,
              const float* __restrict__ qvec,
              float* __restrict__ scoreOut, int bShift)
{
    gemm_body<MODE>(A, B, C, M, N, K, vvec, qvec, scoreOut, bShift, blockIdx.y, 0, K);
}

// dual-mode kernel (doc side): two jobs drained as one CTA pool
template<int MODE_A, int MODE_B>
__global__ __launch_bounds__(128, 4)
void sgemm_dual(const float* __restrict__ A1, const float* __restrict__ B1,
                float* __restrict__ C1, int M1,
                const float* __restrict__ A2, const float* __restrict__ B2,
                float* __restrict__ C2, int M2,
                int N, int K, const float* __restrict__ vvec)
{
    const int half = M1 >> 6;
    if ((int)blockIdx.y < half)
        gemm_body<MODE_A>(A1, B1, C1, M1, N, K, vvec, nullptr, nullptr, 0, blockIdx.y, 0, K);
    else
        gemm_body<MODE_B>(A2, B2, C2, M2, N, K, vvec, nullptr, nullptr, 0, blockIdx.y - half, 0, K);
}

// split-K W1 round: partials P[kc] = ni @ W1 (K chunk kc of 4), M=1024
// grid (8, 64): y = kc*16 + bm
__global__ __launch_bounds__(128, 4)
void sgemm_splitk_w1(const float* __restrict__ A, const float* __restrict__ B,
                     float* __restrict__ P)
{
    const int kc = blockIdx.y >> 4, bm = blockIdx.y & 15;
    gemm_body<0>(A, B, P + (size_t)kc * 1048576u, 1024, 1024, 1024,
                 nullptr, nullptr, nullptr, 0, bm, kc * 256, 256);
}

// split-K node dual: job0 = out@W0 -> P[0..3], job1 = out@U3 -> P[4..7]
// grid (8, 128): y = job*64 + kc*16 + bm
__global__ __launch_bounds__(128, 4)
void sgemm_splitk_node(const float* __restrict__ A, const float* __restrict__ BW0,
                       const float* __restrict__ BU3, float* __restrict__ P)
{
    const int job = blockIdx.y >> 6;
    const int rem = blockIdx.y & 63;
    const int kc = rem >> 4, bm = rem & 15;
    const float* B = job ? BU3 : BW0;
    gemm_body<0>(A, B, P + (size_t)(job * 4 + kc) * 1048576u, 1024, 1024, 1024,
                 nullptr, nullptr, nullptr, 0, bm, kc * 256, 256);
}

// reduce 4 partials -> relu  (for W1 rounds): 1M elements, float4 per thread
__global__ __launch_bounds__(256)
void k_reduce_relu(const float* __restrict__ P, float* __restrict__ outp)
{
    const size_t i = ((size_t)blockIdx.x * 256 + threadIdx.x) * 4;
    float4 a = *(const float4*)(P + i);
    float4 b = *(const float4*)(P + 1048576u + i);
    float4 c = *(const float4*)(P + 2097152u + i);
    float4 d = *(const float4*)(P + 3145728u + i);
    float4 o;
    o.x = fmaxf(((a.x + b.x) + c.x) + d.x, 0.f);
    o.y = fmaxf(((a.y + b.y) + c.y) + d.y, 0.f);
    o.z = fmaxf(((a.z + b.z) + c.z) + d.z, 0.f);
    o.w = fmaxf(((a.w + b.w) + c.w) + d.w, 0.f);
    *(float4*)(outp + i) = o;
}

// reduce node partials: job0 -> r2 = relu(sum)*v0[col], job1 -> proj = sum
__global__ __launch_bounds__(256)
void k_reduce_node(const float* __restrict__ P, const float* __restrict__ v0,
                   float* __restrict__ r2, float* __restrict__ proj)
{
    const int job = blockIdx.x >> 10;
    const size_t e = ((size_t)(blockIdx.x & 1023) * 256 + threadIdx.x) * 4;
    const float* Pb = P + (size_t)job * 4194304u;
    float4 a = *(const float4*)(Pb + e);
    float4 b = *(const float4*)(Pb + 1048576u + e);
    float4 c = *(const float4*)(Pb + 2097152u + e);
    float4 d = *(const float4*)(Pb + 3145728u + e);
    float4 s;
    s.x = ((a.x + b.x) + c.x) + d.x;
    s.y = ((a.y + b.y) + c.y) + d.y;
    s.z = ((a.z + b.z) + c.z) + d.z;
    s.w = ((a.w + b.w) + c.w) + d.w;
    if (job == 0) {
        float4 vv = *(const float4*)(v0 + (e & 1023u));
        s.x = fmaxf(s.x, 0.f) * vv.x;
        s.y = fmaxf(s.y, 0.f) * vv.y;
        s.z = fmaxf(s.z, 0.f) * vv.z;
        s.w = fmaxf(s.w, 0.f) * vv.w;
        *(float4*)(r2 + e) = s;
    } else {
        *(float4*)(proj + e) = s;
    }
}

// ---------------- small kernels ---------------------------------------------
__global__ void k_lastdoc(const float* __restrict__ doc, const int* __restrict__ dmask)
{
    int b = blockIdx.x, t = threadIdx.x;
    __shared__ int s_len;
    if (t == 0) s_len = 0;
    __syncthreads();
    int c = 0;
    for (int i = t; i < LDOC; i += 256) c += (dmask[b * LDOC + i] == 0);
#pragma unroll
    for (int o = 16; o; o >>= 1) c += __shfl_down_sync(0xffffffffu, c, o);
    if ((t & 31) == 0) atomicAdd(&s_len, c);
    __syncthreads();
    int idx = s_len - 1;
    for (int i = t; i < HDIM; i += 256)
        g_lastdoc[b * HDIM + i] = doc[((size_t)b * LDOC + idx) * HDIM + i];
}

__global__ void k_q(const float* __restrict__ W2, const float* __restrict__ v2)
{
    int c = blockIdx.x * 256 + threadIdx.x;
    int b = blockIdx.y;
    const float* ld = &g_lastdoc[b * HDIM];
    float acc = 0.f;
    for (int k = 0; k < HDIM; k += 4) {
        float4 x = *(const float4*)&ld[k];
        acc += x.x * W2[(size_t)(k + 0) * HDIM + c];
        acc += x.y * W2[(size_t)(k + 1) * HDIM + c];
        acc += x.z * W2[(size_t)(k + 2) * HDIM + c];
        acc += x.w * W2[(size_t)(k + 3) * HDIM + c];
    }
    g_q[b * HDIM + c] = fmaxf(acc, 0.f) * v2[c];
}

__global__ __launch_bounds__(256)
void k_nodeinit(const unsigned char* __restrict__ nmask)
{
    int p = blockIdx.x;
    int t = threadIdx.x;
    __shared__ float e[LCH];
    if (t < 32) {
        float s = 0.f;
#pragma unroll
        for (int cb = 0; cb < 8; cb++) s += g_scorep[cb * 32768 + p * LCH + t];
        if (nmask[p * LCH + t]) s = -INFINITY;
        float mx = s;
#pragma unroll
        for (int o = 16; o; o >>= 1) mx = fmaxf(mx, __shfl_xor_sync(0xffffffffu, mx, o));
        float ex = expf(s - mx);
        float sm = ex;
#pragma unroll
        for (int o = 16; o; o >>= 1) sm += __shfl_xor_sync(0xffffffffu, sm, o);
        e[t] = ex / sm;
    }
    __syncthreads();
    float4 acc = make_float4(0.f, 0.f, 0.f, 0.f);
    const float4* ap = (const float4*)&g_attn[(size_t)p * LCH * HDIM];
#pragma unroll 4
    for (int l = 0; l < LCH; l++) {
        float w = e[l];
        float4 x = ap[l * 256 + t];
        acc.x += w * x.x; acc.y += w * x.y; acc.z += w * x.z; acc.w += w * x.w;
    }
    ((float4*)g_ni0)[(size_t)p * 256 + t] = acc;
}

__global__ __launch_bounds__(256)
void k_round(const float* __restrict__ g, const float* __restrict__ v1,
             const int* __restrict__ edge,
             const float* __restrict__ ni_in, float* __restrict__ ni_out)
{
    int bi = blockIdx.x;
    int b = bi >> 6, i = bi & 63;
    int t = threadIdx.x;
    __shared__ __align__(16) float gv[HDIM];
    __shared__ float sc[64];
    __shared__ float al[64];
    {
        float4 x  = ((const float4*)g)[(size_t)bi * 256 + t];
        float4 vv = ((const float4*)v1)[t];
        *(float4*)&gv[t * 4] = make_float4(x.x * vv.x, x.y * vv.y, x.z * vv.z, x.w * vv.w);
    }
    __syncthreads();
    int j = t >> 2, sub = t & 3;
    const float* gj = g + (size_t)(b * 64 + j) * HDIM;
    float acc = 0.f;
#pragma unroll 8
    for (int it = 0; it < 64; it++) {
        int h = it * 16 + sub * 4;
        float4 a  = *(const float4*)&gj[h];
        float4 bb = *(const float4*)&gv[h];
        acc += a.x * bb.x + a.y * bb.y + a.z * bb.z + a.w * bb.w;
    }
    acc += __shfl_xor_sync(0xffffffffu, acc, 1);
    acc += __shfl_xor_sync(0xffffffffu, acc, 2);
    if (sub == 0) sc[j] = acc;
    __syncthreads();
    if (t < 32) {
        const int* er = edge + (size_t)(b * 64 + i) * 64;
        float s0 = sc[t], s1 = sc[t + 32];
        if (er[t] == 0)      s0 = -100000.0f;
        if (er[t + 32] == 0) s1 = -100000.0f;
        float mx = fmaxf(s0, s1);
#pragma unroll
        for (int o = 16; o; o >>= 1) mx = fmaxf(mx, __shfl_xor_sync(0xffffffffu, mx, o));
        float e0 = expf(s0 - mx), e1 = expf(s1 - mx);
        float sm = e0 + e1;
#pragma unroll
        for (int o = 16; o; o >>= 1) sm += __shfl_xor_sync(0xffffffffu, sm, o);
        float inv = 1.f / sm;
        al[t] = e0 * inv; al[t + 32] = e1 * inv;
    }
    __syncthreads();
    float4 a4 = make_float4(0.f, 0.f, 0.f, 0.f);
    const float4* nib = (const float4*)(ni_in + (size_t)b * 64 * HDIM);
#pragma unroll 4
    for (int jj = 0; jj < 64; jj++) {
        float w = al[jj];
        float4 x = nib[jj * 256 + t];
        a4.x += w * x.x; a4.y += w * x.y; a4.z += w * x.z; a4.w += w * x.w;
    }
    ((float4*)ni_out)[(size_t)bi * 256 + t] = a4;
}

__global__ void k_fmask(const int* __restrict__ edge)
{
    int t = threadIdx.x;
    const int* er = edge + (size_t)t * 64;
    int s = 0;
#pragma unroll 8
    for (int jj = 0; jj < 64; jj++) s += er[jj];
    g_fm[t] = (s == 0);
}

__global__ __launch_bounds__(256)
void k_docattn(float* __restrict__ out)
{
    const int bidx = blockIdx.x;
    const int b = bidx >> 5;
    const int ld0 = (bidx & 31) * 32;
    const int tid = threadIdx.x;
    const int tx = tid & 15, ty = tid >> 4;
    __shared__ __align__(16) float sAl[32][68];
    __shared__ __align__(16) float buf[8448];
    float* r1cT = buf;            // [64 k][36]
    float* r2cT = buf + 2304;     // [64 k][68]

    float acc0[4] = {0.f, 0.f, 0.f, 0.f};
    float acc1[4] = {0.f, 0.f, 0.f, 0.f};

    for (int kc = 0; kc < 16; kc++) {
#pragma unroll
        for (int it = 0; it < 2; it++) {
            int f = tid + it * 256;
            int row = f >> 4, c4 = f & 15;
            float4 v = *(const float4*)&g_r1W0[((size_t)(b * 1024 + ld0 + row)) * 1024 + kc * 64 + c4 * 4];
            r1cT[(c4 * 4 + 0) * 36 + row] = v.x;
            r1cT[(c4 * 4 + 1) * 36 + row] = v.y;
            r1cT[(c4 * 4 + 2) * 36 + row] = v.z;
            r1cT[(c4 * 4 + 3) * 36 + row] = v.w;
        }
#pragma unroll
        for (int it = 0; it < 4; it++) {
            int f = tid + it * 256;
            int jj = f >> 4, c4 = f & 15;
            float4 v = *(const float4*)&g_r2W0[((size_t)(b * 64 + jj)) * 1024 + kc * 64 + c4 * 4];
            r2cT[(c4 * 4 + 0) * 68 + jj] = v.x;
            r2cT[(c4 * 4 + 1) * 68 + jj] = v.y;
            r2cT[(c4 * 4 + 2) * 68 + jj] = v.z;
            r2cT[(c4 * 4 + 3) * 68 + jj] = v.w;
        }
        __syncthreads();
#pragma unroll
        for (int k = 0; k < 64; k++) {
            float a0 = r1cT[k * 36 + ty * 2];
            float a1 = r1cT[k * 36 + ty * 2 + 1];
            float4 bb = *(float4*)&r2cT[k * 68 + tx * 4];
            acc0[0] += a0 * bb.x; acc0[1] += a0 * bb.y; acc0[2] += a0 * bb.z; acc0[3] += a0 * bb.w;
            acc1[0] += a1 * bb.x; acc1[1] += a1 * bb.y; acc1[2] += a1 * bb.z; acc1[3] += a1 * bb.w;
        }
        __syncthreads();
    }
    *(float4*)&sAl[ty * 2][tx * 4]     = *(float4*)&acc0[0];
    *(float4*)&sAl[ty * 2 + 1][tx * 4] = *(float4*)&acc1[0];
    __syncthreads();

    {
        int w = tid >> 5, lane = tid & 31;
        int m0 = g_fm[b * 64 + lane];
        int m1 = g_fm[b * 64 + lane + 32];
#pragma unroll
        for (int r = 0; r < 4; r++) {
            int row = w * 4 + r;
            float v0 = sAl[row][lane];
            float v1 = sAl[row][lane + 32];
            if (m0) v0 = -INFINITY;
            if (m1) v1 = -INFINITY;
            float mx = fmaxf(v0, v1);
#pragma unroll
            for (int o = 16; o; o >>= 1) mx = fmaxf(mx, __shfl_xor_sync(0xffffffffu, mx, o));
            float e0 = expf(v0 - mx), e1 = expf(v1 - mx);
            float sm = e0 + e1;
#pragma unroll
            for (int o = 16; o; o >>= 1) sm += __shfl_xor_sync(0xffffffffu, sm, o);
            float inv = 1.f / sm;
            sAl[row][lane] = e0 * inv;
            sAl[row][lane + 32] = e1 * inv;
        }
    }
    __syncthreads();

    float* projc = buf;
    for (int nc = 0; nc < 8; nc++) {
#pragma unroll
        for (int it = 0; it < 8; it++) {
            int f = tid + it * 256;
            int jj = f >> 5, c4 = f & 31;
            float4 v = *(const float4*)&g_proj[((size_t)(b * 64 + jj)) * 1024 + nc * 128 + c4 * 4];
            *(float4*)&projc[jj * 132 + c4 * 4] = v;
        }
        __syncthreads();
        float o0[8] = {0.f,0.f,0.f,0.f,0.f,0.f,0.f,0.f};
        float o1[8] = {0.f,0.f,0.f,0.f,0.f,0.f,0.f,0.f};
#pragma unroll
        for (int jj = 0; jj < 64; jj++) {
            float a0 = sAl[ty * 2][jj];
            float a1 = sAl[ty * 2 + 1][jj];
            float4 p0 = *(float4*)&projc[jj * 132 + tx * 4];
            float4 p1 = *(float4*)&projc[jj * 132 + 64 + tx * 4];
            o0[0] += a0 * p0.x; o0[1] += a0 * p0.y; o0[2] += a0 * p0.z; o0[3] += a0 * p0.w;
            o0[4] += a0 * p1.x; o0[5] += a0 * p1.y; o0[6] += a0 * p1.z; o0[7] += a0 * p1.w;
            o1[0] += a1 * p0.x; o1[1] += a1 * p0.y; o1[2] += a1 * p0.z; o1[3] += a1 * p0.w;
            o1[4] += a1 * p1.x; o1[5] += a1 * p1.y; o1[6] += a1 * p1.z; o1[7] += a1 * p1.w;
        }
#pragma unroll
        for (int r = 0; r < 2; r++) {
            float* src = r ? o1 : o0;
            float* op = out + ((size_t)(b * 1024 + ld0 + ty * 2 + r)) * 1024 + nc * 128;
            float4 c0 = *(float4*)(op + tx * 4);
            c0.x += src[0]; c0.y += src[1]; c0.z += src[2]; c0.w += src[3];
            *(float4*)(op + tx * 4) = c0;
            float4 c1 = *(float4*)(op + 64 + tx * 4);
            c1.x += src[4]; c1.y += src[5]; c1.z += src[6]; c1.w += src[7];
            *(float4*)(op + 64 + tx * 4) = c1;
        }
        __syncthreads();
    }
}

// ---------------- launch -----------------------------------------------------
extern "C" void kernel_launch(void* const* d_in, const int* in_sizes, int n_in,
                              void* d_out, int out_size)
{
    const float* doc   = (const float*)d_in[0];
    const float* node  = (const float*)d_in[1];
    const float* Wn    = (const float*)d_in[2];
    const float* U3    = (const float*)d_in[3];
    const float* U4    = (const float*)d_in[4];
    const float* W2    = (const float*)d_in[5];
    const float* v2    = (const float*)d_in[6];
    const float* W1    = (const float*)d_in[7];
    const float* v1    = (const float*)d_in[8];
    const float* W0    = (const float*)d_in[9];
    const float* v0    = (const float*)d_in[10];
    const int* dmask   = (const int*)d_in[11];
    const unsigned char* nmask = (const unsigned char*)d_in[12];
    const int* edge    = (const int*)d_in[13];
    float* out = (float*)d_out;
    (void)in_sizes; (void)n_in; (void)out_size;

    float *p_attn, *p_scorep, *p_ni0, *p_ni1, *p_g, *p_r2, *p_proj, *p_r1, *p_q, *p_pk;
    cudaGetSymbolAddress((void**)&p_attn,   g_attn);
    cudaGetSymbolAddress((void**)&p_scorep, g_scorep);
    cudaGetSymbolAddress((void**)&p_ni0,    g_ni0);
    cudaGetSymbolAddress((void**)&p_ni1,    g_ni1);
    cudaGetSymbolAddress((void**)&p_g,      g_g);
    cudaGetSymbolAddress((void**)&p_r2,     g_r2W0);
    cudaGetSymbolAddress((void**)&p_proj,   g_proj);
    cudaGetSymbolAddress((void**)&p_r1,     g_r1W0);
    cudaGetSymbolAddress((void**)&p_q,      g_q);
    cudaGetSymbolAddress((void**)&p_pk,     g_pk);

    cudaFuncSetAttribute(sgemm128<0>, cudaFuncAttributeMaxDynamicSharedMemorySize, SMEM_GB);
    cudaFuncSetAttribute(sgemm128<3>, cudaFuncAttributeMaxDynamicSharedMemorySize, SMEM_GB);
    cudaFuncSetAttribute(sgemm_dual<0, 1>, cudaFuncAttributeMaxDynamicSharedMemorySize, SMEM_GB);
    cudaFuncSetAttribute(sgemm_splitk_w1, cudaFuncAttributeMaxDynamicSharedMemorySize, SMEM_GB);
    cudaFuncSetAttribute(sgemm_splitk_node, cudaFuncAttributeMaxDynamicSharedMemorySize, SMEM_GB);

    k_lastdoc<<<BSZ, 256>>>(doc, dmask);
    k_q<<<dim3(4, BSZ), 256>>>(W2, v2);

    // G1: attn_node = node_emb @ weightnode   [32768,1024]
    sgemm128<0><<<dim3(8, 512), 128, SMEM_GB>>>(node, Wn, p_attn, 32768, 1024, 1024,
                                                nullptr, nullptr, nullptr, 0);
    // G2: fused relu(attn_node @ W2) . q -> partial scores
    sgemm128<3><<<dim3(8, 512), 128, SMEM_GB>>>(p_attn, W2, nullptr, 32768, 1024, 1024,
                                                nullptr, p_q, p_scorep, 11);

    k_nodeinit<<<1024, 256>>>(nmask);

    // 3 GAT rounds — W1 GEMM via split-K (512 CTAs = full wave) + reduce
    const float* cur = p_ni0; float* nxt = p_ni1;
    for (int r = 0; r < 3; r++) {
        sgemm_splitk_w1<<<dim3(8, 64), 128, SMEM_GB>>>(cur, W1, p_pk);
        k_reduce_relu<<<1024, 256>>>(p_pk, p_g);
        k_round<<<1024, 256>>>(p_g, v1, edge, cur, nxt);
        const float* tmp = cur; cur = nxt; nxt = (float*)tmp;
    }

    // node-side projections via split-K dual (1024 CTAs) + fused reduce
    sgemm_splitk_node<<<dim3(8, 128), 128, SMEM_GB>>>(cur, W0, U3, p_pk);
    k_reduce_node<<<2048, 256>>>(p_pk, v0, p_r2, p_proj);

    // doc-side merged: out = doc@U4  +  r1W0 = relu(doc@W0)
    sgemm_dual<0, 1><<<dim3(8, 512), 128, SMEM_GB>>>(doc, U4, out, 16384,
                                                     doc, W0, p_r1, 16384,
                                                     1024, 1024, nullptr);

    k_fmask<<<1, 1024>>>(edge);
    k_docattn<<<512, 256>>>(out);
}